// round 9
// baseline (speedup 1.0000x reference)
#include <cuda_runtime.h>

#define BB   8
#define CIN  32
#define COUT 32
#define HH   128
#define WW   128
#define SS   1024
#define JJ   (HH*WW)
#define NBA  256     // kernel A blocks (one per (b,i))

// Scratch: fully overwritten every launch. g_cnt is a monotone arrival
// counter (advances by exactly NBA per launch -> replay-safe last-block
// detection, no reset needed).
__device__ float  g_T[BB*CIN];
__device__ float  g_U[BB*CIN];
__device__ float  g_V[BB*CIN];
__device__ float4 g_PQR[BB*COUT];     // per-plane (P,Q,R,0)
__device__ unsigned int g_cnt;

// ---------------------------------------------------------------------------
// Kernel A: gather-reduce T/U/V (one block per (b,i)); the LAST block to
// finish additionally computes P/Q/R for all 256 output planes. PDL trigger
// is issued after all of this block's global writes.
// ---------------------------------------------------------------------------
__global__ void __launch_bounds__(256) nystrom_reduce_tuv(
    const float* __restrict__ v,
    const float* __restrict__ weight,   // [COUT, CIN, 2]
    const int*   __restrict__ idx32)    // int32 or int64 (detected)
{
    const int bi  = blockIdx.x;            // b*32 + i
    const float* plane = v + (size_t)bi * JJ;
    const int tid  = threadIdx.x;
    const int lane = tid & 31;
    const int warp = tid >> 5;

    // indices are a permutation (distinct); three zeros at int32 positions
    // 1,3,5 can only be int64 high-halves.
    const bool is64 = (idx32[1] == 0) && (idx32[3] == 0) && (idx32[5] == 0);

    const float step = 2.0f / 127.0f;
    float t = 0.f, u = 0.f, w = 0.f;

    #pragma unroll
    for (int k = 0; k < 4; ++k) {
        const int s = tid + k * 256;
        const int j = is64 ? idx32[2 * s] : idx32[s];
        const float x = -1.0f + step * (float)(j & (WW - 1));
        const float y = -1.0f + step * (float)(j >> 7);
        const float val = __ldg(plane + j);
        t += val;
        u  = fmaf(x, val, u);
        w  = fmaf(y, val, w);
    }

    #pragma unroll
    for (int off = 16; off > 0; off >>= 1) {
        t += __shfl_down_sync(0xffffffffu, t, off);
        u += __shfl_down_sync(0xffffffffu, u, off);
        w += __shfl_down_sync(0xffffffffu, w, off);
    }
    __shared__ float sred[3][8];
    __shared__ int   s_last;
    if (lane == 0) { sred[0][warp] = t; sred[1][warp] = u; sred[2][warp] = w; }
    __syncthreads();
    if (warp == 0) {
        float T = (lane < 8) ? sred[0][lane] : 0.f;
        float U = (lane < 8) ? sred[1][lane] : 0.f;
        float V = (lane < 8) ? sred[2][lane] : 0.f;
        #pragma unroll
        for (int off = 4; off > 0; off >>= 1) {
            T += __shfl_down_sync(0xffffffffu, T, off);
            U += __shfl_down_sync(0xffffffffu, U, off);
            V += __shfl_down_sync(0xffffffffu, V, off);
        }
        if (lane == 0) { g_T[bi] = T; g_U[bi] = U; g_V[bi] = V; }
    }

    // Last-block detection (monotone counter, replay-safe).
    if (tid == 0) {
        __threadfence();                                 // release this block's T/U/V
        const unsigned int old = atomicAdd(&g_cnt, 1u);
        s_last = ((old % NBA) == NBA - 1u);
    }
    __syncthreads();

    if (s_last) {
        __threadfence();                                 // acquire all blocks' T/U/V
        // One thread per output plane: serial 32-term dot (L2-hit loads, MLP).
        const int b = tid >> 5;
        const int o = tid & 31;
        const float* wr = weight + o * (CIN * 2);
        float P = 0.f, Q = 0.f, R = 0.f;
        #pragma unroll
        for (int i = 0; i < CIN; ++i) {
            const float Ti = __ldcg(g_T + b * CIN + i);
            const float Ui = __ldcg(g_U + b * CIN + i);
            const float Vi = __ldcg(g_V + b * CIN + i);
            const float w0 = __ldg(wr + 2 * i);
            const float w1 = __ldg(wr + 2 * i + 1);
            P = fmaf(Ti, w0, P);
            Q = fmaf(Ti, w1, Q);
            R = fmaf(Ui, w0, fmaf(Vi, w1, R));
        }
        g_PQR[tid] = make_float4(P, Q, R, 0.f);
        __threadfence();                                 // publish before trigger
    }

#if defined(__CUDA_ARCH__) && (__CUDA_ARCH__ >= 900)
    cudaTriggerProgrammaticLaunchCompletion();
#endif
}

// ---------------------------------------------------------------------------
// Kernel B: output fill. Preamble = ONE float4 L2 load. 2 blocks per plane;
// warp = row; constant-stride STG.128 body (1 FMA + 4 FADD + 1 STG per f4).
// ---------------------------------------------------------------------------
__global__ void __launch_bounds__(256) nystrom_fill(
    float* __restrict__ out)            // [B, COUT, H, W]
{
    const int plane = blockIdx.x >> 1;   // b*32 + o
    const int half  = blockIdx.x & 1;
    const int tid  = threadIdx.x;
    const int lane = tid & 31;
    const int warp = tid >> 5;
    const float step = 2.0f / 127.0f;

    // Address/coordinate setup (independent of kernel A -> overlaps under PDL).
    const int r0 = half * 64 + warp;                    // starting row
    float4* outp = (float4*)(out + (size_t)plane * JJ) + r0 * 32 + lane;
    const float x0 = -1.0f + step * (float)(lane * 4);
    const float y0 = -1.0f + step * (float)r0;

#if defined(__CUDA_ARCH__) && (__CUDA_ARCH__ >= 900)
    cudaGridDependencySynchronize();
#endif

    const float4 pqr = __ldcg(&g_PQR[plane]);
    const float P = pqr.x, Q = pqr.y, R = pqr.z;

    float4 xp;
    xp.x = x0 * P;
    xp.y = fmaf(step,        P, xp.x);
    xp.z = fmaf(2.0f * step, P, xp.x);
    xp.w = fmaf(3.0f * step, P, xp.x);

    const float base0 = fmaf(y0, Q, -R);
    const float dbase = 8.0f * step * Q;               // 8-row stride per iter

    #pragma unroll
    for (int k = 0; k < 8; ++k) {
        const float base = fmaf((float)k, dbase, base0);
        float4 o4;
        o4.x = xp.x + base;
        o4.y = xp.y + base;
        o4.z = xp.z + base;
        o4.w = xp.w + base;
        outp[k * 256] = o4;                            // STG.128 [ptr+imm]
    }
}

extern "C" void kernel_launch(void* const* d_in, const int* in_sizes, int n_in,
                              void* d_out, int out_size)
{
    const float* v      = (const float*)d_in[0];
    const float* weight = (const float*)d_in[1];
    const int*   idx32  = (const int*)  d_in[2];
    float*       out    = (float*)d_out;

    nystrom_reduce_tuv<<<NBA, 256>>>(v, weight, idx32);

    cudaLaunchConfig_t cfg = {};
    cfg.gridDim  = dim3(BB * COUT * 2);   // 512 blocks
    cfg.blockDim = dim3(256);
    cfg.dynamicSmemBytes = 0;
    cfg.stream = 0;
    cudaLaunchAttribute attr[1];
    attr[0].id = cudaLaunchAttributeProgrammaticStreamSerialization;
    attr[0].val.programmaticStreamSerializationAllowed = 1;
    cfg.attrs = attr;
    cfg.numAttrs = 1;
    cudaLaunchKernelEx(&cfg, nystrom_fill, (float*)out);
}

// round 11
// speedup vs baseline: 1.3907x; 1.3907x over previous
#include <cuda_runtime.h>
#include <cstdint>

#define BB   8
#define CIN  32
#define COUT 32
#define HH   128
#define WW   128
#define SS   1024
#define JJ   (HH*WW)

__device__ __forceinline__ uint32_t smem_u32(const void* p) {
    uint32_t a;
    asm("{ .reg .u64 t; cvta.to.shared.u64 t, %1; cvt.u32.u64 %0, t; }"
        : "=r"(a) : "l"(p));
    return a;
}
__device__ __forceinline__ uint32_t mapa_rank(uint32_t a, uint32_t r) {
    uint32_t o;
    asm("mapa.shared::cluster.u32 %0, %1, %2;" : "=r"(o) : "r"(a), "r"(r));
    return o;
}
__device__ __forceinline__ float ld_cluster_f32(uint32_t a) {
    float v;
    asm volatile("ld.shared::cluster.f32 %0, [%1];" : "=f"(v) : "r"(a));
    return v;
}
__device__ __forceinline__ uint32_t ctarank() {
    uint32_t r;
    asm("mov.u32 %0, %%cluster_ctarank;" : "=r"(r));
    return r;
}

// Grid 256, block 256, cluster 8. Cluster c = (batch b=c/4, quarter q=c%4).
// Block rank r: gathers channels r*4..r*4+3 of batch b into its smem,
// cluster.sync, reads all 32 channels' T/U/V via DSMEM, fills plane
// (b, o=q*8+r). Trailing cluster barrier keeps every CTA's SMEM alive until
// all peers' DSMEM reads are done.
__global__ void __launch_bounds__(256) __cluster_dims__(8, 1, 1)
nystrom_cluster(const float* __restrict__ v,        // [B, CIN, H, W]
                const float* __restrict__ weight,   // [COUT, CIN, 2]
                const int*   __restrict__ idx32,    // int32 or int64 (detected)
                float*       __restrict__ out)      // [B, COUT, H, W]
{
    __shared__ float sTUV[4][3];     // this block's 4 channels: T,U,V
    __shared__ float part[8][3];     // per-warp partials

    const int tid  = threadIdx.x;
    const int lane = tid & 31;
    const int warp = tid >> 5;

    const int rank = (int)ctarank();         // 0..7 within cluster
    const int c    = blockIdx.x >> 3;        // cluster index 0..31
    const int b    = c >> 2;                 // batch 0..7
    const int q    = c & 3;                  // quarter 0..3
    const int o    = q * 8 + rank;           // output plane this block fills
    const int i0   = rank * 4;               // first gathered channel

    // indices are a permutation (distinct); three zeros at int32 positions
    // 1,3,5 can only be int64 high-halves.
    const bool is64 = (idx32[1] == 0) && (idx32[3] == 0) && (idx32[5] == 0);
    const float step = 2.0f / 127.0f;

    // ---------- Phase 1: gather 4 channels (64 threads per channel) ----------
    {
        const int ch  = tid >> 6;    // 0..3
        const int t64 = tid & 63;
        const float* plane = v + (size_t)(b * CIN + i0 + ch) * JJ;

        float t = 0.f, u = 0.f, w = 0.f;
        #pragma unroll
        for (int k = 0; k < 16; ++k) {
            const int s = t64 + k * 64;
            const int j = is64 ? idx32[2 * s] : idx32[s];
            const float x = -1.0f + step * (float)(j & (WW - 1));
            const float y = -1.0f + step * (float)(j >> 7);
            const float val = __ldg(plane + j);
            t += val;
            u  = fmaf(x, val, u);
            w  = fmaf(y, val, w);
        }
        #pragma unroll
        for (int off = 16; off > 0; off >>= 1) {
            t += __shfl_down_sync(0xffffffffu, t, off);
            u += __shfl_down_sync(0xffffffffu, u, off);
            w += __shfl_down_sync(0xffffffffu, w, off);
        }
        if (lane == 0) { part[warp][0] = t; part[warp][1] = u; part[warp][2] = w; }
        __syncthreads();
        if (tid < 4) {               // combine the channel's two warp partials
            sTUV[tid][0] = part[2 * tid][0] + part[2 * tid + 1][0];
            sTUV[tid][1] = part[2 * tid][1] + part[2 * tid + 1][1];
            sTUV[tid][2] = part[2 * tid][2] + part[2 * tid + 1][2];
        }
    }

    // Weight preload (independent of phase 1; overlaps barrier skew).
    const float2 wv = ((const float2*)weight)[o * CIN + lane];

    // ---------- Cluster barrier: smem writes visible to DSMEM readers --------
    asm volatile("barrier.cluster.arrive.aligned;" ::: "memory");
    asm volatile("barrier.cluster.wait.aligned;"   ::: "memory");

    // ---------- Phase 2: warp-dot over DSMEM, then fill one plane -------------
    // Lane = channel. Channel i lives in cluster block (i>>2), slot (i&3).
    const uint32_t la = smem_u32(&sTUV[lane & 3][0]);
    const uint32_t ra = mapa_rank(la, (uint32_t)(lane >> 2));
    const float T = ld_cluster_f32(ra);
    const float U = ld_cluster_f32(ra + 4);
    const float V = ld_cluster_f32(ra + 8);

    float p  = T * wv.x;
    float qq = T * wv.y;
    float r  = fmaf(U, wv.x, V * wv.y);
    #pragma unroll
    for (int off = 16; off > 0; off >>= 1) {
        p  += __shfl_xor_sync(0xffffffffu, p,  off);
        qq += __shfl_xor_sync(0xffffffffu, qq, off);
        r  += __shfl_xor_sync(0xffffffffu, r,  off);
    }
    const float P = p, Q = qq, R = r;

    const int pl = b * COUT + o;
    float4* outp = (float4*)(out + (size_t)pl * JJ);
    #pragma unroll
    for (int k = 0; k < 16; ++k) {
        const int q4 = tid + k * 256;          // float4 index in plane [0,4096)
        const int h  = q4 >> 5;
        const int wq = (q4 * 4) & (WW - 1);
        const float y = -1.0f + step * (float)h;
        const float base = fmaf(y, Q, -R);
        const float x0 = -1.0f + step * (float)wq;
        float4 o4;
        o4.x = fmaf(x0,               P, base);
        o4.y = fmaf(x0 +        step, P, base);
        o4.z = fmaf(x0 + 2.0f * step, P, base);
        o4.w = fmaf(x0 + 3.0f * step, P, base);
        outp[q4] = o4;
    }

    // ---------- Trailing cluster barrier: keep SMEM alive for peers ----------
    // (All DSMEM reads above complete before any CTA in the cluster exits.)
    asm volatile("barrier.cluster.arrive.aligned;" ::: "memory");
    asm volatile("barrier.cluster.wait.aligned;"   ::: "memory");
}

extern "C" void kernel_launch(void* const* d_in, const int* in_sizes, int n_in,
                              void* d_out, int out_size)
{
    const float* v      = (const float*)d_in[0];
    const float* weight = (const float*)d_in[1];
    const int*   idx32  = (const int*)  d_in[2];
    float*       out    = (float*)d_out;

    // Static __cluster_dims__(8,1,1); plain launch is valid and capturable.
    nystrom_cluster<<<BB * COUT, 256>>>(v, weight, idx32, out);
}

// round 12
// speedup vs baseline: 1.9552x; 1.4060x over previous
#include <cuda_runtime.h>
#include <cstdint>

#define BB   8
#define CIN  32
#define COUT 32
#define HH   128
#define WW   128
#define SS   1024
#define JJ   (HH*WW)

// Scratch: fully overwritten every launch (deterministic across graph replays).
__device__ float g_T[BB*CIN];
__device__ float g_U[BB*CIN];
__device__ float g_V[BB*CIN];

__device__ __forceinline__ uint32_t smem_u32(const void* p) {
    uint32_t a;
    asm("{ .reg .u64 t; cvta.to.shared.u64 t, %1; cvt.u32.u64 %0, t; }"
        : "=r"(a) : "l"(p));
    return a;
}

// ---------------------------------------------------------------------------
// Kernel A: one block per (b,i). T/U/V gather-reductions. (R6 version, proven.)
// ---------------------------------------------------------------------------
__global__ void __launch_bounds__(256) nystrom_reduce_tuv(
    const float* __restrict__ v,
    const int*   __restrict__ idx32)   // int32 or int64 (detected)
{
    const int bi  = blockIdx.x;            // b*32 + i
    const float* plane = v + (size_t)bi * JJ;
    const int tid  = threadIdx.x;
    const int lane = tid & 31;
    const int warp = tid >> 5;

    // indices are a permutation (distinct); three zeros at int32 positions
    // 1,3,5 can only be int64 high-halves.
    const bool is64 = (idx32[1] == 0) && (idx32[3] == 0) && (idx32[5] == 0);

    const float step = 2.0f / 127.0f;
    float t = 0.f, u = 0.f, w = 0.f;

    #pragma unroll
    for (int k = 0; k < 4; ++k) {
        const int s = tid + k * 256;
        const int j = is64 ? idx32[2 * s] : idx32[s];
        const float x = -1.0f + step * (float)(j & (WW - 1));
        const float y = -1.0f + step * (float)(j >> 7);
        const float val = __ldg(plane + j);
        t += val;
        u  = fmaf(x, val, u);
        w  = fmaf(y, val, w);
    }

    #pragma unroll
    for (int off = 16; off > 0; off >>= 1) {
        t += __shfl_down_sync(0xffffffffu, t, off);
        u += __shfl_down_sync(0xffffffffu, u, off);
        w += __shfl_down_sync(0xffffffffu, w, off);
    }
    __shared__ float sred[3][8];
    if (lane == 0) { sred[0][warp] = t; sred[1][warp] = u; sred[2][warp] = w; }
    __syncthreads();
    if (warp == 0) {
        float T = (lane < 8) ? sred[0][lane] : 0.f;
        float U = (lane < 8) ? sred[1][lane] : 0.f;
        float V = (lane < 8) ? sred[2][lane] : 0.f;
        #pragma unroll
        for (int off = 4; off > 0; off >>= 1) {
            T += __shfl_down_sync(0xffffffffu, T, off);
            U += __shfl_down_sync(0xffffffffu, U, off);
            V += __shfl_down_sync(0xffffffffu, V, off);
        }
        if (lane == 0) { g_T[bi] = T; g_U[bi] = U; g_V[bi] = V; }
    }
    __syncthreads();

#if defined(__CUDA_ARCH__) && (__CUDA_ARCH__ >= 900)
    __threadfence();
    cudaTriggerProgrammaticLaunchCompletion();
#endif
}

// ---------------------------------------------------------------------------
// Kernel B: fill one plane per block via SMEM staging + cp.async.bulk stores.
// 4 chunks of 16KB (32 rows), double-buffered; TMA engine drains SMEM->L2,
// bypassing the per-warp STG store-queue path.
// ---------------------------------------------------------------------------
__global__ void __launch_bounds__(256) nystrom_fill_tma(
    const float* __restrict__ weight,   // [COUT, CIN, 2]
    float*       __restrict__ out)      // [B, COUT, H, W]
{
    __shared__ __align__(128) float buf[2][32 * WW];   // 2 x 16KB

    const int plane = blockIdx.x;        // b*32 + o
    const int b = plane >> 5;
    const int o = plane & 31;
    const int tid  = threadIdx.x;
    const int lane = tid & 31;
    const float step = 2.0f / 127.0f;

    // Weight load + setup overlap kernel A under PDL.
    const float2 wv = ((const float2*)weight)[o * CIN + lane];
    float* gdst = out + (size_t)plane * JJ;

#if defined(__CUDA_ARCH__) && (__CUDA_ARCH__ >= 900)
    cudaGridDependencySynchronize();
#endif

    // Warp-parallel dot: lane = channel.
    const float T = __ldcg(g_T + b * CIN + lane);
    const float U = __ldcg(g_U + b * CIN + lane);
    const float V = __ldcg(g_V + b * CIN + lane);

    float p  = T * wv.x;
    float qd = T * wv.y;
    float r  = fmaf(U, wv.x, V * wv.y);
    #pragma unroll
    for (int off = 16; off > 0; off >>= 1) {
        p  += __shfl_xor_sync(0xffffffffu, p,  off);
        qd += __shfl_xor_sync(0xffffffffu, qd, off);
        r  += __shfl_xor_sync(0xffffffffu, r,  off);
    }
    const float P = p, Q = qd, R = r;

    // Loop-invariant x-part for this thread's column group (col4 = tid&31).
    const int col4 = tid & 31;                    // float4 column within row
    const float x0 = -1.0f + step * (float)(col4 * 4);
    float4 xp;
    xp.x = x0 * P;
    xp.y = fmaf(step,        P, xp.x);
    xp.z = fmaf(2.0f * step, P, xp.x);
    xp.w = fmaf(3.0f * step, P, xp.x);
    const int row_in_chunk0 = tid >> 5;           // 0..7 (thread covers 4 rows, stride 8)

    #pragma unroll
    for (int c = 0; c < 4; ++c) {
        // Before overwriting buffer (c&1), make sure chunk c-2's store drained.
        if (c >= 2) {
            if (tid == 0)
                asm volatile("cp.async.bulk.wait_group 1;" ::: "memory");
            __syncthreads();
        }

        float4* sbuf = (float4*)buf[c & 1];
        #pragma unroll
        for (int k = 0; k < 4; ++k) {
            const int rowc = row_in_chunk0 + k * 8;        // row within chunk 0..31
            const int h = c * 32 + rowc;                   // global row
            const float y = -1.0f + step * (float)h;
            const float base = fmaf(y, Q, -R);
            float4 o4;
            o4.x = xp.x + base;
            o4.y = xp.y + base;
            o4.z = xp.z + base;
            o4.w = xp.w + base;
            sbuf[rowc * 32 + col4] = o4;                   // STS.128
        }
        __syncthreads();

        if (tid == 0) {
            asm volatile("fence.proxy.async.shared::cta;" ::: "memory");
            asm volatile(
                "cp.async.bulk.global.shared::cta.bulk_group [%0], [%1], %2;"
                :: "l"(gdst + c * 32 * WW), "r"(smem_u32(buf[c & 1])),
                   "r"(32 * WW * 4)
                : "memory");
            asm volatile("cp.async.bulk.commit_group;" ::: "memory");
        }
    }

    // Drain all outstanding bulk stores before exit.
    if (tid == 0)
        asm volatile("cp.async.bulk.wait_group 0;" ::: "memory");
}

extern "C" void kernel_launch(void* const* d_in, const int* in_sizes, int n_in,
                              void* d_out, int out_size)
{
    const float* v      = (const float*)d_in[0];
    const float* weight = (const float*)d_in[1];
    const int*   idx32  = (const int*)  d_in[2];
    float*       out    = (float*)d_out;

    nystrom_reduce_tuv<<<BB * CIN, 256>>>(v, idx32);

    cudaLaunchConfig_t cfg = {};
    cfg.gridDim  = dim3(BB * COUT);      // 256 blocks, one plane each
    cfg.blockDim = dim3(256);
    cfg.dynamicSmemBytes = 0;
    cfg.stream = 0;
    cudaLaunchAttribute attr[1];
    attr[0].id = cudaLaunchAttributeProgrammaticStreamSerialization;
    attr[0].val.programmaticStreamSerializationAllowed = 1;
    cfg.attrs = attr;
    cfg.numAttrs = 1;
    cudaLaunchKernelEx(&cfg, nystrom_fill_tma, weight, (float*)out);
}